// round 4
// baseline (speedup 1.0000x reference)
#include <cuda_runtime.h>
#include <cstdint>

#define N_NODES 50000
#define N_FEAT  500
#define HID     256        // N_HID * N_HEAD
#define N_HEAD  4
#define HEAD_C  64
#define E_RAW   800000
#define E_TOT   850000     // + self loops
#define CATW    768        // HID * 3 layers
#define N_CLASS 40

// ------------------------------------------------------------------
// Scratch (device globals; referenced by symbol ONLY inside kernels)
// ------------------------------------------------------------------
__device__ float g_z[N_NODES * HID];          // per-layer projected features
__device__ float g_hcat[N_NODES * CATW];      // JK concat buffer (layer outputs)
__device__ float g_es[N_NODES * N_HEAD];      // attention src scores
__device__ float g_ed[N_NODES * N_HEAD];      // attention dst scores
__device__ int   g_off[N_NODES + 1];          // CSR offsets (by dst)
__device__ int   g_cur[N_NODES];              // deg -> cursor
__device__ int   g_ssrc[E_TOT];               // src ids grouped by dst

__device__ __forceinline__ int clampN(int v) {
    return v < 0 ? 0 : (v >= N_NODES ? N_NODES - 1 : v);
}

// ------------------------------------------------------------------
// CSR construction  (edge_index arrives as int32: JAX x64-disabled
// downcasts the reference's int64 request)
// ------------------------------------------------------------------
__global__ void zero_kernel() {
    int i = blockIdx.x * blockDim.x + threadIdx.x;
    if (i < N_NODES) g_cur[i] = 0;
}

__global__ void hist_kernel(const int* __restrict__ ei) {
    int e = blockIdx.x * blockDim.x + threadIdx.x;
    if (e >= E_TOT) return;
    int d = (e < E_RAW) ? clampN(ei[E_RAW + e]) : (e - E_RAW);
    atomicAdd(&g_cur[d], 1);
}

// Single-block exclusive scan over 50000 counts; writes g_off and cursor copy.
__global__ void scan_kernel() {
    __shared__ int sh[1024];
    int t = threadIdx.x;
    int carry = 0;
    for (int base = 0; base < N_NODES; base += 1024) {
        int i = base + t;
        int v = (i < N_NODES) ? g_cur[i] : 0;
        sh[t] = v;
        __syncthreads();
        #pragma unroll
        for (int o = 1; o < 1024; o <<= 1) {
            int add = (t >= o) ? sh[t - o] : 0;
            __syncthreads();
            sh[t] += add;
            __syncthreads();
        }
        int incl = sh[t];
        int total = sh[1023];
        if (i < N_NODES) {
            int excl = carry + incl - v;
            g_off[i] = excl;
            g_cur[i] = excl;   // becomes scatter cursor
        }
        carry += total;
        __syncthreads();
    }
    if (t == 0) g_off[N_NODES] = carry;
}

__global__ void scatter_kernel(const int* __restrict__ ei) {
    int e = blockIdx.x * blockDim.x + threadIdx.x;
    if (e >= E_TOT) return;
    int s, d;
    if (e < E_RAW) { s = clampN(ei[e]); d = clampN(ei[E_RAW + e]); }
    else           { s = d = e - E_RAW; }
    int p = atomicAdd(&g_cur[d], 1);
    if (p < E_TOT) g_ssrc[p] = s;
}

// ------------------------------------------------------------------
// Tiled fp32 GEMM: C[M,N] = A[M,K] @ B[K,N] (+ optional bias)
// A source: a_sel==0 -> A_in (harness ptr), a_sel==1 -> g_hcat + a_off
// C dest:   c_sel==0 -> g_z,  c_sel==1 -> C_out (harness ptr)
// BM=128, BN=64, BK=16, TM=8, TN=4, 256 threads (16x16)
// ------------------------------------------------------------------
#define BM 128
#define BN 64
#define BK 16
#define TM 8
#define TN 4

__global__ void sgemm_kernel(const float* __restrict__ A_in, int a_sel, long long a_off, int lda,
                             const float* __restrict__ B, int ldb,
                             float* __restrict__ C_out, int c_sel, int ldc,
                             int M, int N, int K,
                             const float* __restrict__ bias) {
    const float* A = (a_sel == 0) ? A_in : (g_hcat + a_off);
    float*       C = (c_sel == 0) ? g_z  : C_out;

    __shared__ float As[BK][BM + 1];
    __shared__ float Bs[BK][BN];

    int tx = threadIdx.x, ty = threadIdx.y;
    int tid = ty * 16 + tx;
    int block_row = blockIdx.y * BM;
    int block_col = blockIdx.x * BN;

    float acc[TM][TN];
    #pragma unroll
    for (int i = 0; i < TM; i++)
        #pragma unroll
        for (int j = 0; j < TN; j++) acc[i][j] = 0.f;

    int a_k  = tid % BK;      // 0..15
    int a_r0 = tid / BK;      // 0..15
    int b_c  = tid % BN;      // 0..63
    int b_r0 = tid / BN;      // 0..3

    for (int k0 = 0; k0 < K; k0 += BK) {
        #pragma unroll
        for (int i = 0; i < 8; i++) {
            int r  = a_r0 + i * 16;
            int gr = block_row + r;
            int gk = k0 + a_k;
            As[a_k][r] = (gr < M && gk < K) ? A[(size_t)gr * lda + gk] : 0.f;
        }
        #pragma unroll
        for (int i = 0; i < 4; i++) {
            int kk = b_r0 + i * 4;
            int gk = k0 + kk;
            int gc = block_col + b_c;
            Bs[kk][b_c] = (gk < K && gc < N) ? B[(size_t)gk * ldb + gc] : 0.f;
        }
        __syncthreads();

        #pragma unroll
        for (int k = 0; k < BK; k++) {
            float ra[TM], rb[TN];
            #pragma unroll
            for (int i = 0; i < TM; i++) ra[i] = As[k][ty * TM + i];
            #pragma unroll
            for (int j = 0; j < TN; j++) rb[j] = Bs[k][tx * TN + j];
            #pragma unroll
            for (int i = 0; i < TM; i++)
                #pragma unroll
                for (int j = 0; j < TN; j++)
                    acc[i][j] += ra[i] * rb[j];
        }
        __syncthreads();
    }

    #pragma unroll
    for (int i = 0; i < TM; i++) {
        int r = block_row + ty * TM + i;
        if (r >= M) continue;
        #pragma unroll
        for (int j = 0; j < TN; j++) {
            int c = block_col + tx * TN + j;
            if (c >= N) continue;
            float v = acc[i][j];
            if (bias) v += bias[c];
            C[(size_t)r * ldc + c] = v;
        }
    }
}

// ------------------------------------------------------------------
// Attention scores: es[n,h] = dot(z[n,h,:], a_src[h,:]); ed likewise.
// One warp per (node, head).
// ------------------------------------------------------------------
__global__ void escore_kernel(const float* __restrict__ a_src,
                              const float* __restrict__ a_dst) {
    int w    = (blockIdx.x * blockDim.x + threadIdx.x) >> 5;
    int lane = threadIdx.x & 31;
    if (w >= N_NODES * N_HEAD) return;
    int n = w >> 2;
    int h = w & 3;
    const float* zp = g_z + (size_t)n * HID + h * HEAD_C;
    float z0 = zp[lane], z1 = zp[lane + 32];
    float s  = z0 * a_src[h * HEAD_C + lane] + z1 * a_src[h * HEAD_C + lane + 32];
    float dv = z0 * a_dst[h * HEAD_C + lane] + z1 * a_dst[h * HEAD_C + lane + 32];
    #pragma unroll
    for (int o = 16; o > 0; o >>= 1) {
        s  += __shfl_xor_sync(0xFFFFFFFFu, s, o);
        dv += __shfl_xor_sync(0xFFFFFFFFu, dv, o);
    }
    if (lane == 0) { g_es[w] = s; g_ed[w] = dv; }
}

// ------------------------------------------------------------------
// Fused online-softmax aggregation per (dst node, head).
// Warp = (node, head). 2 nodes per 256-thread block.
// Writes g_hcat layer slice (row stride CATW). Bias + ReLU applied.
// ------------------------------------------------------------------
__global__ void aggregate_kernel(const float* __restrict__ bias, int layer) {
    int w    = threadIdx.x >> 5;       // 0..7
    int lane = threadIdx.x & 31;
    int node = blockIdx.x * 2 + (w >> 2);
    int h    = w & 3;
    if (node >= N_NODES) return;

    int start = g_off[node];
    int end   = g_off[node + 1];
    float edv = g_ed[node * N_HEAD + h];

    float m = -3.0e38f, dsum = 0.f, a0 = 0.f, a1 = 0.f;
    for (int e = start; e < end; e++) {
        int s = g_ssrc[e];
        float ev = g_es[s * N_HEAD + h] + edv;
        ev = ev > 0.f ? ev : 0.2f * ev;               // leaky_relu(0.2)
        const float* zp = g_z + (size_t)s * HID + h * HEAD_C;
        float z0 = zp[lane];
        float z1 = zp[lane + 32];
        if (ev > m) {
            float sc = __expf(m - ev);
            dsum *= sc; a0 *= sc; a1 *= sc; m = ev;
        }
        float wt = __expf(ev - m);
        dsum += wt;
        a0 += wt * z0;
        a1 += wt * z1;
    }
    float inv = 1.f / (dsum + 1e-16f);
    int c = h * HEAD_C + lane;
    float o0 = fmaxf(a0 * inv + bias[c], 0.f);
    float o1 = fmaxf(a1 * inv + bias[c + 32], 0.f);
    float* out = g_hcat + (size_t)layer * HID;
    out[(size_t)node * CATW + c]      = o0;
    out[(size_t)node * CATW + c + 32] = o1;
}

// ------------------------------------------------------------------
// Launch
// ------------------------------------------------------------------
extern "C" void kernel_launch(void* const* d_in, const int* in_sizes, int n_in,
                              void* d_out, int out_size) {
    const float* x   = (const float*)d_in[0];
    const int*   ei  = (const int*)d_in[1];     // int32 (JAX x64-disabled)
    const float* W[3]  = { (const float*)d_in[2],  (const float*)d_in[6],  (const float*)d_in[10] };
    const float* AS[3] = { (const float*)d_in[3],  (const float*)d_in[7],  (const float*)d_in[11] };
    const float* AD[3] = { (const float*)d_in[4],  (const float*)d_in[8],  (const float*)d_in[12] };
    const float* BB[3] = { (const float*)d_in[5],  (const float*)d_in[9],  (const float*)d_in[13] };
    const float* Wout  = (const float*)d_in[14];
    const float* bout  = (const float*)d_in[15];

    // --- CSR by dst (self loops appended) ---
    zero_kernel<<<(N_NODES + 255) / 256, 256>>>();
    hist_kernel<<<(E_TOT + 255) / 256, 256>>>(ei);
    scan_kernel<<<1, 1024>>>();
    scatter_kernel<<<(E_TOT + 255) / 256, 256>>>(ei);

    dim3 tb(16, 16);
    int mblocks = (N_NODES + BM - 1) / BM;                   // 391
    int warp_blocks = (N_NODES * N_HEAD * 32 + 255) / 256;   // 25000
    int agg_blocks  = (N_NODES + 1) / 2;                     // 25000

    // --- 3 GAT layers ---
    for (int l = 0; l < 3; l++) {
        int a_sel       = (l == 0) ? 0 : 1;
        long long a_off = (l == 0) ? 0 : (long long)(l - 1) * HID;
        int lda         = (l == 0) ? N_FEAT : CATW;
        int K           = (l == 0) ? N_FEAT : HID;
        sgemm_kernel<<<dim3(HID / BN, mblocks), tb>>>(
            x, a_sel, a_off, lda,
            W[l], HID,
            nullptr, /*c_sel=*/0, HID,
            N_NODES, HID, K, nullptr);
        escore_kernel<<<warp_blocks, 256>>>(AS[l], AD[l]);
        aggregate_kernel<<<agg_blocks, 256>>>(BB[l], l);
    }

    // --- JK cat -> output projection (to harness d_out) ---
    sgemm_kernel<<<dim3((N_CLASS + BN - 1) / BN, mblocks), tb>>>(
        nullptr, /*a_sel=*/1, 0, CATW,
        Wout, N_CLASS,
        (float*)d_out, /*c_sel=*/1, N_CLASS,
        N_NODES, N_CLASS, CATW, bout);
}

// round 5
// speedup vs baseline: 1.4619x; 1.4619x over previous
#include <cuda_runtime.h>
#include <cstdint>

#define N_NODES 50000
#define N_FEAT  500
#define HID     256        // N_HID * N_HEAD
#define N_HEAD  4
#define HEAD_C  64
#define E_RAW   800000
#define E_TOT   850000     // + self loops
#define CATW    768        // HID * 3 layers
#define N_CLASS 40

// ------------------------------------------------------------------
// Scratch (device globals; referenced by symbol ONLY inside kernels)
// ------------------------------------------------------------------
__device__ float g_z[N_NODES * HID];
__device__ float g_hcat[N_NODES * CATW];
__device__ float g_es[N_NODES * N_HEAD];
__device__ float g_ed[N_NODES * N_HEAD];
__device__ int   g_off[N_NODES + 1];
__device__ int   g_cur[N_NODES];
__device__ int   g_ssrc[E_TOT];

__device__ __forceinline__ int clampN(int v) {
    return v < 0 ? 0 : (v >= N_NODES ? N_NODES - 1 : v);
}

// ------------------------------------------------------------------
// CSR construction (edge_index is int32 on device)
// ------------------------------------------------------------------
__global__ void zero_kernel() {
    int i = blockIdx.x * blockDim.x + threadIdx.x;
    if (i < N_NODES) g_cur[i] = 0;
}

__global__ void hist_kernel(const int* __restrict__ ei) {
    int e = blockIdx.x * blockDim.x + threadIdx.x;
    if (e >= E_TOT) return;
    int d = (e < E_RAW) ? clampN(ei[E_RAW + e]) : (e - E_RAW);
    atomicAdd(&g_cur[d], 1);
}

__global__ void scan_kernel() {
    __shared__ int sh[1024];
    int t = threadIdx.x;
    int carry = 0;
    for (int base = 0; base < N_NODES; base += 1024) {
        int i = base + t;
        int v = (i < N_NODES) ? g_cur[i] : 0;
        sh[t] = v;
        __syncthreads();
        #pragma unroll
        for (int o = 1; o < 1024; o <<= 1) {
            int add = (t >= o) ? sh[t - o] : 0;
            __syncthreads();
            sh[t] += add;
            __syncthreads();
        }
        int incl = sh[t];
        int total = sh[1023];
        if (i < N_NODES) {
            int excl = carry + incl - v;
            g_off[i] = excl;
            g_cur[i] = excl;
        }
        carry += total;
        __syncthreads();
    }
    if (t == 0) g_off[N_NODES] = carry;
}

__global__ void scatter_kernel(const int* __restrict__ ei) {
    int e = blockIdx.x * blockDim.x + threadIdx.x;
    if (e >= E_TOT) return;
    int s, d;
    if (e < E_RAW) { s = clampN(ei[e]); d = clampN(ei[E_RAW + e]); }
    else           { s = d = e - E_RAW; }
    int p = atomicAdd(&g_cur[d], 1);
    if (p < E_TOT) g_ssrc[p] = s;
}

// ------------------------------------------------------------------
// tf32 tensor-core GEMM: C[M,N] = A[M,K] @ B[K,N] (+ optional bias)
// Block tile 128x64x32, 8 warps (4 along M x 2 along N), warp tile 32x32.
// mma.sync.aligned.m16n8k8.row.col.f32.tf32.tf32.f32
// smem stride 36 -> conflict-free fragment reads ((4n+k)%32 distinct).
// ------------------------------------------------------------------
#define TBM 128
#define TBN 64
#define TBK 32
#define SSTR 36

__device__ __forceinline__ uint32_t f2tf32(float v) {
    uint32_t u;
    asm("cvt.rna.tf32.f32 %0, %1;" : "=r"(u) : "f"(v));
    return u;
}

__device__ __forceinline__ void mma_tf32(float& d0, float& d1, float& d2, float& d3,
                                         uint32_t a0, uint32_t a1, uint32_t a2, uint32_t a3,
                                         uint32_t b0, uint32_t b1) {
    asm volatile(
        "mma.sync.aligned.m16n8k8.row.col.f32.tf32.tf32.f32 "
        "{%0,%1,%2,%3}, {%4,%5,%6,%7}, {%8,%9}, {%0,%1,%2,%3};\n"
        : "+f"(d0), "+f"(d1), "+f"(d2), "+f"(d3)
        : "r"(a0), "r"(a1), "r"(a2), "r"(a3), "r"(b0), "r"(b1));
}

__global__ void tgemm_kernel(const float* __restrict__ A_in, int a_sel, long long a_off, int lda,
                             const float* __restrict__ B, int ldb,
                             float* __restrict__ C_out, int c_sel, int ldc,
                             int M, int N, int K,
                             const float* __restrict__ bias) {
    const float* A = (a_sel == 0) ? A_in : (g_hcat + a_off);
    float*       C = (c_sel == 0) ? g_z  : C_out;

    __shared__ uint32_t As[TBM * SSTR];   // [row][k]
    __shared__ uint32_t Bs[TBN * SSTR];   // [n][k] (transposed on store)

    int tid  = threadIdx.x;
    int wid  = tid >> 5;
    int lane = tid & 31;
    int wm   = wid & 3;           // 0..3  (M direction)
    int wn   = wid >> 2;          // 0..1  (N direction)
    int g    = lane >> 2;         // 0..7
    int t    = lane & 3;          // 0..3

    int brow = blockIdx.y * TBM;
    int bcol = blockIdx.x * TBN;

    float acc[2][4][4];
    #pragma unroll
    for (int i = 0; i < 2; i++)
        #pragma unroll
        for (int j = 0; j < 4; j++)
            #pragma unroll
            for (int r = 0; r < 4; r++) acc[i][j][r] = 0.f;

    int a_r0 = tid >> 5;          // 0..7, +8 per chunk
    int a_k  = tid & 31;
    int b_n  = tid & 63;          // 0..63
    int b_k0 = tid >> 6;          // 0..3, +4 per chunk

    for (int k0 = 0; k0 < K; k0 += TBK) {
        // Load A tile 128x32 (16 elems/thread), coalesced along k.
        #pragma unroll
        for (int i = 0; i < 16; i++) {
            int r  = a_r0 + i * 8;
            int gr = brow + r;
            int gk = k0 + a_k;
            float v = (gr < M && gk < K) ? A[(size_t)gr * lda + gk] : 0.f;
            As[r * SSTR + a_k] = f2tf32(v);
        }
        // Load B tile 32x64 (8 elems/thread), coalesced along n, stored [n][k].
        #pragma unroll
        for (int i = 0; i < 8; i++) {
            int kk = b_k0 + i * 4;
            int gk = k0 + kk;
            int gn = bcol + b_n;
            float v = (gk < K && gn < N) ? B[(size_t)gk * ldb + gn] : 0.f;
            Bs[b_n * SSTR + kk] = f2tf32(v);
        }
        __syncthreads();

        #pragma unroll
        for (int ks = 0; ks < 4; ks++) {
            int kb = ks * 8;
            uint32_t af[2][4];
            #pragma unroll
            for (int mt = 0; mt < 2; mt++) {
                int r = wm * 32 + mt * 16 + g;
                af[mt][0] = As[r * SSTR + kb + t];
                af[mt][1] = As[(r + 8) * SSTR + kb + t];
                af[mt][2] = As[r * SSTR + kb + t + 4];
                af[mt][3] = As[(r + 8) * SSTR + kb + t + 4];
            }
            uint32_t bf[4][2];
            #pragma unroll
            for (int nt = 0; nt < 4; nt++) {
                int n = wn * 32 + nt * 8 + g;
                bf[nt][0] = Bs[n * SSTR + kb + t];
                bf[nt][1] = Bs[n * SSTR + kb + t + 4];
            }
            #pragma unroll
            for (int mt = 0; mt < 2; mt++)
                #pragma unroll
                for (int nt = 0; nt < 4; nt++)
                    mma_tf32(acc[mt][nt][0], acc[mt][nt][1], acc[mt][nt][2], acc[mt][nt][3],
                             af[mt][0], af[mt][1], af[mt][2], af[mt][3],
                             bf[nt][0], bf[nt][1]);
        }
        __syncthreads();
    }

    // Epilogue: c0:(g,2t) c1:(g,2t+1) c2:(g+8,2t) c3:(g+8,2t+1)
    #pragma unroll
    for (int mt = 0; mt < 2; mt++) {
        int r0 = brow + wm * 32 + mt * 16 + g;
        #pragma unroll
        for (int nt = 0; nt < 4; nt++) {
            int c0 = bcol + wn * 32 + nt * 8 + 2 * t;
            float bv0 = 0.f, bv1 = 0.f;
            if (bias) {
                if (c0 < N)     bv0 = bias[c0];
                if (c0 + 1 < N) bv1 = bias[c0 + 1];
            }
            if (r0 < M) {
                if (c0 < N)     C[(size_t)r0 * ldc + c0]     = acc[mt][nt][0] + bv0;
                if (c0 + 1 < N) C[(size_t)r0 * ldc + c0 + 1] = acc[mt][nt][1] + bv1;
            }
            if (r0 + 8 < M) {
                if (c0 < N)     C[(size_t)(r0 + 8) * ldc + c0]     = acc[mt][nt][2] + bv0;
                if (c0 + 1 < N) C[(size_t)(r0 + 8) * ldc + c0 + 1] = acc[mt][nt][3] + bv1;
            }
        }
    }
}

// ------------------------------------------------------------------
// Attention scores: one warp per (node, head).
// ------------------------------------------------------------------
__global__ void escore_kernel(const float* __restrict__ a_src,
                              const float* __restrict__ a_dst) {
    int w    = (blockIdx.x * blockDim.x + threadIdx.x) >> 5;
    int lane = threadIdx.x & 31;
    if (w >= N_NODES * N_HEAD) return;
    int n = w >> 2;
    int h = w & 3;
    const float* zp = g_z + (size_t)n * HID + h * HEAD_C;
    float z0 = zp[lane], z1 = zp[lane + 32];
    float s  = z0 * a_src[h * HEAD_C + lane] + z1 * a_src[h * HEAD_C + lane + 32];
    float dv = z0 * a_dst[h * HEAD_C + lane] + z1 * a_dst[h * HEAD_C + lane + 32];
    #pragma unroll
    for (int o = 16; o > 0; o >>= 1) {
        s  += __shfl_xor_sync(0xFFFFFFFFu, s, o);
        dv += __shfl_xor_sync(0xFFFFFFFFu, dv, o);
    }
    if (lane == 0) { g_es[w] = s; g_ed[w] = dv; }
}

// ------------------------------------------------------------------
// Fused online-softmax aggregation per (dst node, head).
// ------------------------------------------------------------------
__global__ void aggregate_kernel(const float* __restrict__ bias, int layer) {
    int w    = threadIdx.x >> 5;
    int lane = threadIdx.x & 31;
    int node = blockIdx.x * 2 + (w >> 2);
    int h    = w & 3;
    if (node >= N_NODES) return;

    int start = g_off[node];
    int end   = g_off[node + 1];
    float edv = g_ed[node * N_HEAD + h];

    float m = -3.0e38f, dsum = 0.f, a0 = 0.f, a1 = 0.f;
    for (int e = start; e < end; e++) {
        int s = g_ssrc[e];
        float ev = g_es[s * N_HEAD + h] + edv;
        ev = ev > 0.f ? ev : 0.2f * ev;
        const float* zp = g_z + (size_t)s * HID + h * HEAD_C;
        float z0 = zp[lane];
        float z1 = zp[lane + 32];
        if (ev > m) {
            float sc = __expf(m - ev);
            dsum *= sc; a0 *= sc; a1 *= sc; m = ev;
        }
        float wt = __expf(ev - m);
        dsum += wt;
        a0 += wt * z0;
        a1 += wt * z1;
    }
    float inv = 1.f / (dsum + 1e-16f);
    int c = h * HEAD_C + lane;
    float o0 = fmaxf(a0 * inv + bias[c], 0.f);
    float o1 = fmaxf(a1 * inv + bias[c + 32], 0.f);
    float* out = g_hcat + (size_t)layer * HID;
    out[(size_t)node * CATW + c]      = o0;
    out[(size_t)node * CATW + c + 32] = o1;
}

// ------------------------------------------------------------------
// Launch
// ------------------------------------------------------------------
extern "C" void kernel_launch(void* const* d_in, const int* in_sizes, int n_in,
                              void* d_out, int out_size) {
    const float* x   = (const float*)d_in[0];
    const int*   ei  = (const int*)d_in[1];
    const float* W[3]  = { (const float*)d_in[2],  (const float*)d_in[6],  (const float*)d_in[10] };
    const float* AS[3] = { (const float*)d_in[3],  (const float*)d_in[7],  (const float*)d_in[11] };
    const float* AD[3] = { (const float*)d_in[4],  (const float*)d_in[8],  (const float*)d_in[12] };
    const float* BB[3] = { (const float*)d_in[5],  (const float*)d_in[9],  (const float*)d_in[13] };
    const float* Wout  = (const float*)d_in[14];
    const float* bout  = (const float*)d_in[15];

    // --- CSR by dst ---
    zero_kernel<<<(N_NODES + 255) / 256, 256>>>();
    hist_kernel<<<(E_TOT + 255) / 256, 256>>>(ei);
    scan_kernel<<<1, 1024>>>();
    scatter_kernel<<<(E_TOT + 255) / 256, 256>>>(ei);

    int mblocks     = (N_NODES + TBM - 1) / TBM;             // 391
    int warp_blocks = (N_NODES * N_HEAD * 32 + 255) / 256;   // 25000
    int agg_blocks  = (N_NODES + 1) / 2;                     // 25000

    // --- 3 GAT layers ---
    for (int l = 0; l < 3; l++) {
        int a_sel       = (l == 0) ? 0 : 1;
        long long a_off = (l == 0) ? 0 : (long long)(l - 1) * HID;
        int lda         = (l == 0) ? N_FEAT : CATW;
        int K           = (l == 0) ? N_FEAT : HID;
        tgemm_kernel<<<dim3(HID / TBN, mblocks), 256>>>(
            x, a_sel, a_off, lda,
            W[l], HID,
            nullptr, /*c_sel=*/0, HID,
            N_NODES, HID, K, nullptr);
        escore_kernel<<<warp_blocks, 256>>>(AS[l], AD[l]);
        aggregate_kernel<<<agg_blocks, 256>>>(BB[l], l);
    }

    // --- JK cat -> output projection ---
    tgemm_kernel<<<dim3((N_CLASS + TBN - 1) / TBN, mblocks), 256>>>(
        nullptr, /*a_sel=*/1, 0, CATW,
        Wout, N_CLASS,
        (float*)d_out, /*c_sel=*/1, N_CLASS,
        N_NODES, N_CLASS, CATW, bout);
}